// round 7
// baseline (speedup 1.0000x reference)
#include <cuda_runtime.h>
#include <math_constants.h>

// Roi_61564061221098 round 7: vectorized R4.
// Warp = (roi, 4 channels). Load phase: lane=(ch<<3)|colgroup, each lane does
// LDG.128 -> one instruction per row covers 4 channels x 32 columns. Window
// base aligned to 4 floats (w0a) so all float4 loads are 16B aligned
// (row stride 68 floats = 17 float4 exactly). Reduce phase as R4: ch=lane>>3,
// pw=lane&7, 4 channels reduced in parallel. Stripes templated (1/2/3).

#define NC    512
#define FH    50
#define FW    68
#define PLANE (FH * FW)
#define PP    7
#define SCALE 0.0625f
#define NEG_INF (-CUDART_INF_F)

// packed per-roi record: [0]=base(n*NC*PLANE + w0a), [1]=spanA(=we6-w0a),
// [2]=maxw, [3..9] = hs | he<<8 | (ws-w0a)<<16 | (we-w0a)<<24
__device__ __align__(16) int g_rec[4096 * 16];

__global__ void roi_prep(const float* __restrict__ rois,
                         const int*   __restrict__ ridx, int R)
{
    int r = blockIdx.x * blockDim.x + threadIdx.x;
    if (r >= R) return;

    const float y1 = rois[r * 4 + 0];
    const float x1 = rois[r * 4 + 1];
    const float y2 = rois[r * 4 + 2];
    const float x2 = rois[r * 4 + 3];
    const float rb0 = rintf(__fmul_rn(x1, SCALE));
    const float rb1 = rintf(__fmul_rn(y1, SCALE));
    const float rb2 = rintf(__fmul_rn(x2, SCALE));
    const float rb3 = rintf(__fmul_rn(y2, SCALE));
    const float roiw = fmaxf(__fadd_rn(__fsub_rn(rb2, rb0), 1.0f), 1.0f);
    const float roih = fmaxf(__fadd_rn(__fsub_rn(rb3, rb1), 1.0f), 1.0f);
    const float R7 = (float)(1.0 / 7.0);          // XLA: x/7 -> x * fl(1/7)
    const float bw = __fmul_rn(roiw, R7);
    const float bh = __fmul_rn(roih, R7);

    const int w0  = (int)fminf(fmaxf(rb0, 0.0f), (float)FW);  // == ws[0]
    const int w0a = w0 & ~3;                                  // 16B-aligned base
    int maxw = 0;
    int pack[PP];
#pragma unroll
    for (int p = 0; p < PP; p++) {
        const float fp  = (float)p;
        const float fp1 = (float)(p + 1);
        int hs = (int)fminf(fmaxf(__fadd_rn(floorf(__fmul_rn(fp,  bh)), rb1), 0.0f), (float)FH);
        int he = (int)fminf(fmaxf(__fadd_rn(ceilf (__fmul_rn(fp1, bh)), rb1), 0.0f), (float)FH);
        int ws = (int)fminf(fmaxf(__fadd_rn(floorf(__fmul_rn(fp,  bw)), rb0), 0.0f), (float)FW);
        int we = (int)fminf(fmaxf(__fadd_rn(ceilf (__fmul_rn(fp1, bw)), rb0), 0.0f), (float)FW);
        maxw = max(maxw, we - ws);
        pack[p] = hs | (he << 8) | ((ws - w0a) << 16) | ((we - w0a) << 24);
    }
    int* rec = g_rec + r * 16;
    rec[0] = ridx[r] * (NC * PLANE) + w0a;
    rec[1] = (pack[PP - 1] >> 24) & 0xff;     // spanA
    rec[2] = maxw;
#pragma unroll
    for (int p = 0; p < PP; p++) rec[3 + p] = pack[p];
}

__device__ __forceinline__ void fmax4(float4& a, const float4 b)
{
    a.x = fmaxf(a.x, b.x); a.y = fmaxf(a.y, b.y);
    a.z = fmaxf(a.z, b.z); a.w = fmaxf(a.w, b.w);
}

// scol layout: per warp, channel stride 100 floats (16B multiple, pad vs conflicts)
template <int NIT>
__device__ __forceinline__ void pool_warp(const float4* __restrict__ fv,
                                          int v, int spanA, int maxw, int lane,
                                          float* __restrict__ scol,
                                          float* __restrict__ sout)
{
    const int ch = lane >> 3;
    const int cg = lane & 7;           // load-phase column group (4 cols each)
    const int pw = lane & 7;           // reduce-phase pw bin
    const int mypk = __shfl_sync(0xffffffffu, v, 3 + (pw < PP ? pw : 0));
    const int j0 = (mypk >> 16) & 0xff;
    const int j1 = (mypk >> 24) & 0xff;

    // per-lane plane base: channel ch, colgroup cg (row stride = 17 float4)
    const float4* __restrict__ fp = fv + ch * (PLANE / 4) + cg;

    bool act[NIT];
#pragma unroll
    for (int it = 0; it < NIT; it++) act[it] = (it * 32 + cg * 4) < spanA;

#pragma unroll
    for (int ph = 0; ph < PP; ph++) {
        const int pk = __shfl_sync(0xffffffffu, v, 3 + ph);
        const int h0 = pk & 0xff;
        const int h1 = (pk >> 8) & 0xff;
        const int nrow = h1 - h0;

#pragma unroll
        for (int it = 0; it < NIT; it++) {
            float4 m0 = make_float4(NEG_INF, NEG_INF, NEG_INF, NEG_INF);
            float4 m1 = m0;
            if (act[it]) {
                const float4* p = fp + h0 * (FW / 4) + it * 8;
                int h = 0;
                for (; h + 2 <= nrow; h += 2) {         // 2x unroll: MLP + short dep chain
                    fmax4(m0, p[0]);
                    fmax4(m1, p[FW / 4]);
                    p += 2 * (FW / 4);
                }
                if (h < nrow) fmax4(m0, p[0]);
                fmax4(m0, m1);
            }
            *(float4*)(scol + ch * 100 + it * 32 + cg * 4) = m0;   // STS.128
        }
        __syncwarp();

        // 4-channel-parallel per-pw reduce
        float mm = NEG_INF;
        const float* s = scol + ch * 100;
        for (int k = 0; k < maxw; k++) {
            const int j = j0 + k;
            if (j < j1) mm = fmaxf(mm, s[j]);
        }
        if (pw < PP)
            sout[ch * 49 + ph * PP + pw] = (mm == NEG_INF) ? 0.0f : mm;
        __syncwarp();
    }
}

__global__ __launch_bounds__(256, 6)
void roi_pool(const float* __restrict__ x, float* __restrict__ out, int R)
{
    __shared__ float s_col[8][4 * 100];
    __shared__ float s_out[8][200];

    const int r    = blockIdx.x;
    const int warp = threadIdx.x >> 5;
    const int lane = threadIdx.x & 31;
    const int c0   = blockIdx.y * 32 + warp * 4;   // 16 * 32 = 512 channels

    int v = 0;
    if (lane < 16) v = g_rec[r * 16 + lane];
    const int base  = __shfl_sync(0xffffffffu, v, 0);
    const int spanA = __shfl_sync(0xffffffffu, v, 1);
    const int maxw  = __shfl_sync(0xffffffffu, v, 2);

    // base = n*NC*PLANE + w0a: 16B-aligned (PLANE%4==0, w0a%4==0)
    const float4* fv = (const float4*)(x) + (base >> 2) + c0 * (PLANE / 4);
    float* scol = s_col[warp];
    float* sout = s_out[warp];

    if (spanA <= 32)      pool_warp<1>(fv, v, spanA, maxw, lane, scol, sout);
    else if (spanA <= 64) pool_warp<2>(fv, v, spanA, maxw, lane, scol, sout);
    else                  pool_warp<3>(fv, v, spanA, maxw, lane, scol, sout);

    // 196 contiguous floats per warp
    const long long ob = (long long)r * (NC * 49) + (long long)c0 * 49;
#pragma unroll
    for (int i = 0; i < 7; i++) {
        const int idx = i * 32 + lane;
        if (idx < 196) out[ob + idx] = sout[idx];
    }
}

extern "C" void kernel_launch(void* const* d_in, const int* in_sizes, int n_in,
                              void* d_out, int out_size)
{
    const float* x    = (const float*)d_in[0];
    const float* rois = (const float*)d_in[1];
    const int*   ridx = (const int*)d_in[2];
    float*       out  = (float*)d_out;
    const int R = in_sizes[2];

    roi_prep<<<(R + 255) / 256, 256>>>(rois, ridx, R);
    dim3 grid(R, NC / 32);
    roi_pool<<<grid, 256>>>(x, out, R);
}

// round 8
// speedup vs baseline: 1.6956x; 1.6956x over previous
#include <cuda_runtime.h>
#include <math_constants.h>

// Roi_61564061221098 round 8: R4 design widened to 8 channels per warp.
// Load phase: lanes sweep columns (lane + q*32), 8 LDG.32 per row off one
// address register (channel offsets are immediates). Reduce phase:
// lane = ch(0-7)*4 + slot(0-3); each lane reduces pw=slot and pw=slot+4.

#define NC    512
#define FH    50
#define FW    68
#define PLANE (FH * FW)
#define PP    7
#define SCALE 0.0625f
#define NEG_INF (-CUDART_INF_F)

// packed per-roi record: [0]=base(n*NC*PLANE + w0), [1]=span, [2]=maxw,
// [3..9] = hs | he<<8 | (ws-w0)<<16 | (we-w0)<<24
__device__ __align__(16) int g_rec[4096 * 16];

__global__ void roi_prep(const float* __restrict__ rois,
                         const int*   __restrict__ ridx, int R)
{
    int r = blockIdx.x * blockDim.x + threadIdx.x;
    if (r >= R) return;

    const float y1 = rois[r * 4 + 0];
    const float x1 = rois[r * 4 + 1];
    const float y2 = rois[r * 4 + 2];
    const float x2 = rois[r * 4 + 3];
    const float rb0 = rintf(__fmul_rn(x1, SCALE));
    const float rb1 = rintf(__fmul_rn(y1, SCALE));
    const float rb2 = rintf(__fmul_rn(x2, SCALE));
    const float rb3 = rintf(__fmul_rn(y2, SCALE));
    const float roiw = fmaxf(__fadd_rn(__fsub_rn(rb2, rb0), 1.0f), 1.0f);
    const float roih = fmaxf(__fadd_rn(__fsub_rn(rb3, rb1), 1.0f), 1.0f);
    const float R7 = (float)(1.0 / 7.0);          // XLA: x/7 -> x * fl(1/7)
    const float bw = __fmul_rn(roiw, R7);
    const float bh = __fmul_rn(roih, R7);

    const int w0 = (int)fminf(fmaxf(rb0, 0.0f), (float)FW);   // == ws[0]
    int maxw = 0;
    int pack[PP];
#pragma unroll
    for (int p = 0; p < PP; p++) {
        const float fp  = (float)p;
        const float fp1 = (float)(p + 1);
        int hs = (int)fminf(fmaxf(__fadd_rn(floorf(__fmul_rn(fp,  bh)), rb1), 0.0f), (float)FH);
        int he = (int)fminf(fmaxf(__fadd_rn(ceilf (__fmul_rn(fp1, bh)), rb1), 0.0f), (float)FH);
        int ws = (int)fminf(fmaxf(__fadd_rn(floorf(__fmul_rn(fp,  bw)), rb0), 0.0f), (float)FW);
        int we = (int)fminf(fmaxf(__fadd_rn(ceilf (__fmul_rn(fp1, bw)), rb0), 0.0f), (float)FW);
        maxw = max(maxw, we - ws);
        pack[p] = hs | (he << 8) | ((ws - w0) << 16) | ((we - w0) << 24);
    }
    int* rec = g_rec + r * 16;
    rec[0] = ridx[r] * (NC * PLANE) + w0;
    rec[1] = (pack[PP - 1] >> 24) & 0xff;
    rec[2] = maxw;
#pragma unroll
    for (int p = 0; p < PP; p++) rec[3 + p] = pack[p];
}

template <int NR>
__device__ __forceinline__ void pool_warp(const float* __restrict__ fm,
                                          int v, int span, int maxw, int lane,
                                          float* __restrict__ scol,
                                          float* __restrict__ sout)
{
    const int ch   = lane >> 2;        // reduce-phase channel (0-7)
    const int slot = lane & 3;         // reduce-phase pw slot: pw = slot, slot+4
    const int pkA = __shfl_sync(0xffffffffu, v, 3 + slot);
    const int pkB = __shfl_sync(0xffffffffu, v, 3 + (slot < 3 ? slot + 4 : 6));
    const int j0a = (pkA >> 16) & 0xff, j1a = (pkA >> 24) & 0xff;
    const int j0b = (pkB >> 16) & 0xff, j1b = (pkB >> 24) & 0xff;

    bool act[NR];
#pragma unroll
    for (int q = 0; q < NR; q++) act[q] = (lane + q * 32) < span;

#pragma unroll
    for (int ph = 0; ph < PP; ph++) {
        const int pk = __shfl_sync(0xffffffffu, v, 3 + ph);
        const int h0 = pk & 0xff;
        const int h1 = (pk >> 8) & 0xff;

        float m[NR][8];
#pragma unroll
        for (int q = 0; q < NR; q++)
#pragma unroll
            for (int k = 0; k < 8; k++) m[q][k] = NEG_INF;

        const float* p = fm + h0 * FW;
        for (int h = h0; h < h1; h++, p += FW) {
#pragma unroll
            for (int q = 0; q < NR; q++) {
                if (act[q]) {
#pragma unroll
                    for (int k = 0; k < 8; k++)
                        m[q][k] = fmaxf(m[q][k], __ldg(p + lane + q * 32 + k * PLANE));
                }
            }
        }

        // column maxes -> smem: channel k at scol[k*100 + col]
#pragma unroll
        for (int k = 0; k < 8; k++)
#pragma unroll
            for (int q = 0; q < NR; q++)
                scol[k * 100 + q * 32 + lane] = m[q][k];
        __syncwarp();

        // 8-channel-parallel per-pw reduce (each lane: pw=slot and pw=slot+4)
        float mmA = NEG_INF, mmB = NEG_INF;
        const float* s = scol + ch * 100;
        for (int k2 = 0; k2 < maxw; k2++) {
            const int jA = j0a + k2;
            const int jB = j0b + k2;
            if (jA < j1a) mmA = fmaxf(mmA, s[jA]);
            if (jB < j1b) mmB = fmaxf(mmB, s[jB]);
        }
        sout[ch * 49 + ph * PP + slot] = (mmA == NEG_INF) ? 0.0f : mmA;
        if (slot < 3)
            sout[ch * 49 + ph * PP + slot + 4] = (mmB == NEG_INF) ? 0.0f : mmB;
        __syncwarp();
    }
}

__global__ __launch_bounds__(256, 5)
void roi_pool(const float* __restrict__ x, float* __restrict__ out, int R)
{
    __shared__ float s_col[8][8 * 100];
    __shared__ float s_out[8][400];

    const int r    = blockIdx.x;
    const int warp = threadIdx.x >> 5;
    const int lane = threadIdx.x & 31;
    const int c0   = blockIdx.y * 64 + warp * 8;   // 8 * 64 = 512 channels

    int v = 0;
    if (lane < 16) v = g_rec[r * 16 + lane];
    const int base = __shfl_sync(0xffffffffu, v, 0);
    const int span = __shfl_sync(0xffffffffu, v, 1);
    const int maxw = __shfl_sync(0xffffffffu, v, 2);

    const float* fm   = x + base + c0 * PLANE;     // row 0, col w0, channel c0
    float*       scol = s_col[warp];
    float*       sout = s_out[warp];

    if (span <= 32)      pool_warp<1>(fm, v, span, maxw, lane, scol, sout);
    else if (span <= 64) pool_warp<2>(fm, v, span, maxw, lane, scol, sout);
    else                 pool_warp<3>(fm, v, span, maxw, lane, scol, sout);

    // 392 contiguous floats per warp
    const long long ob = (long long)r * (NC * 49) + (long long)c0 * 49;
#pragma unroll
    for (int i = 0; i < 13; i++) {
        const int idx = i * 32 + lane;
        if (idx < 392) out[ob + idx] = sout[idx];
    }
}

extern "C" void kernel_launch(void* const* d_in, const int* in_sizes, int n_in,
                              void* d_out, int out_size)
{
    const float* x    = (const float*)d_in[0];
    const float* rois = (const float*)d_in[1];
    const int*   ridx = (const int*)d_in[2];
    float*       out  = (float*)d_out;
    const int R = in_sizes[2];

    roi_prep<<<(R + 255) / 256, 256>>>(rois, ridx, R);
    dim3 grid(R, NC / 64);
    roi_pool<<<grid, 256>>>(x, out, R);
}